// round 1
// baseline (speedup 1.0000x reference)
#include <cuda_runtime.h>

// Problem constants
#define B_     256
#define C_IN_  8
#define N_     4096
#define K_     9
#define S_     2
#define C_OUT_ 8

#define THREADS 256
#define NTILE   1024                    // n's per CTA
#define NPT     (NTILE / THREADS)       // 4 n's per thread
#define NBLK    (N_ / NTILE)            // 4 tiles along n

// weight pairs per (s,c,k): C_OUT/2 = 4 x f32x2
#define WPAIRS_PER_CK 4
#define WPAIRS_PER_S  (C_IN_ * K_ * WPAIRS_PER_CK)   // 288
#define W_ELEMS       (S_ * C_IN_ * K_ * C_OUT_)     // 1152 floats

__device__ __forceinline__ unsigned long long splat2(float v) {
    unsigned long long r;
    asm("mov.b64 %0, {%1, %1};" : "=l"(r) : "f"(v));
    return r;
}

__device__ __forceinline__ void fma2(unsigned long long& acc,
                                     unsigned long long a,
                                     unsigned long long b) {
    asm("fma.rn.f32x2 %0, %1, %2, %0;" : "+l"(acc) : "l"(a), "l"(b));
}

__device__ __forceinline__ void unpack2(unsigned long long v, float& lo, float& hi) {
    asm("mov.b64 {%0, %1}, %2;" : "=f"(lo), "=f"(hi) : "l"(v));
}

__global__ __launch_bounds__(THREADS)
void lattice_conv_kernel(const float* __restrict__ x,
                         const int*   __restrict__ nbr,
                         const int*   __restrict__ sub_ids,
                         const float* __restrict__ weight,
                         const float* __restrict__ bias,
                         float*       __restrict__ out)
{
    // Weight pairs (f32x2 over d) + bias pairs in shared memory.
    __shared__ __align__(16) unsigned long long sw[S_ * WPAIRS_PER_S]; // 576 * 8B = 4608B
    __shared__ __align__(16) unsigned long long sb[S_ * WPAIRS_PER_CK]; // 8 * 8B

    const int tid = threadIdx.x;

    // Cooperative copy: weight layout (s, c, k, d) is already d-innermost,
    // so a raw float copy gives correctly packed f32x2 pairs.
    {
        float* swf = reinterpret_cast<float*>(sw);
        #pragma unroll
        for (int i = tid; i < W_ELEMS; i += THREADS) swf[i] = weight[i];
        float* sbf = reinterpret_cast<float*>(sb);
        if (tid < S_ * C_OUT_) sbf[tid] = bias[tid];
    }
    __syncthreads();

    const int b  = blockIdx.y;
    const int n0 = blockIdx.x * NTILE;
    const float* xb = x + (size_t)b * (C_IN_ * N_);
    float* ob_base = out + (size_t)b * (C_OUT_ * N_);

    #pragma unroll
    for (int it = 0; it < NPT; ++it) {
        const int n = n0 + it * THREADS + tid;   // lanes -> consecutive n

        const int s = __ldg(&sub_ids[n]);

        int idx[K_];
        #pragma unroll
        for (int k = 0; k < K_; ++k) idx[k] = __ldg(&nbr[n * K_ + k]);

        // Init accumulators with bias pairs
        unsigned long long acc0 = sb[s * WPAIRS_PER_CK + 0];
        unsigned long long acc1 = sb[s * WPAIRS_PER_CK + 1];
        unsigned long long acc2 = sb[s * WPAIRS_PER_CK + 2];
        unsigned long long acc3 = sb[s * WPAIRS_PER_CK + 3];

        const unsigned long long* wrow = sw + s * WPAIRS_PER_S;

        #pragma unroll
        for (int c = 0; c < C_IN_; ++c) {
            #pragma unroll
            for (int k = 0; k < K_; ++k) {
                const float xv = __ldg(&xb[c * N_ + idx[k]]);
                const unsigned long long x2 = splat2(xv);
                const unsigned long long* w4 = wrow + (c * K_ + k) * WPAIRS_PER_CK;
                // two 128-bit shared loads (16B-aligned: offset is multiple of 32B)
                const ulonglong2 wa = *reinterpret_cast<const ulonglong2*>(w4);
                const ulonglong2 wb = *reinterpret_cast<const ulonglong2*>(w4 + 2);
                fma2(acc0, x2, wa.x);
                fma2(acc1, x2, wa.y);
                fma2(acc2, x2, wb.x);
                fma2(acc3, x2, wb.y);
            }
        }

        // Coalesced stores: lanes are consecutive n for each (b,d) row.
        float lo, hi;
        unpack2(acc0, lo, hi);
        ob_base[0 * N_ + n] = lo;  ob_base[1 * N_ + n] = hi;
        unpack2(acc1, lo, hi);
        ob_base[2 * N_ + n] = lo;  ob_base[3 * N_ + n] = hi;
        unpack2(acc2, lo, hi);
        ob_base[4 * N_ + n] = lo;  ob_base[5 * N_ + n] = hi;
        unpack2(acc3, lo, hi);
        ob_base[6 * N_ + n] = lo;  ob_base[7 * N_ + n] = hi;
    }
}

extern "C" void kernel_launch(void* const* d_in, const int* in_sizes, int n_in,
                              void* d_out, int out_size)
{
    const float* x       = (const float*)d_in[0];   // (B, C_IN, N) f32
    const int*   nbr     = (const int*)  d_in[1];   // (N, K) i32
    const int*   sub_ids = (const int*)  d_in[2];   // (N,) i32
    const float* weight  = (const float*)d_in[3];   // (S, C_IN, K, C_OUT) f32
    const float* bias    = (const float*)d_in[4];   // (S, C_OUT) f32
    float*       out     = (float*)d_out;           // (B, C_OUT, N) f32

    dim3 grid(NBLK, B_);
    lattice_conv_kernel<<<grid, THREADS>>>(x, nbr, sub_ids, weight, bias, out);
}

// round 2
// speedup vs baseline: 2.2666x; 2.2666x over previous
#include <cuda_runtime.h>

// Problem constants
#define B_     256
#define C_IN_  8
#define N_     4096
#define K_     9
#define S_     2
#define C_OUT_ 8

#define THREADS 256
#define NPB     4          // n's per block in main kernel
#define WPAIRS_PER_CK 4    // C_OUT/2 f32x2 pairs per (s,c,k)
#define WPAIRS_PER_S  (C_IN_ * K_ * WPAIRS_PER_CK)   // 288
#define W_ELEMS       (S_ * C_IN_ * K_ * C_OUT_)     // 1152 floats

// Scratch (device globals: allocation-free rule)
__device__ float g_xT[C_IN_ * N_ * B_];     // (c, n, b)  33.5 MB
__device__ float g_outT[C_OUT_ * N_ * B_];  // (d, n, b)  33.5 MB

__device__ __forceinline__ unsigned long long splat2(float v) {
    unsigned long long r;
    asm("mov.b64 %0, {%1, %1};" : "=l"(r) : "f"(v));
    return r;
}
__device__ __forceinline__ void fma2(unsigned long long& acc,
                                     unsigned long long a,
                                     unsigned long long b) {
    asm("fma.rn.f32x2 %0, %1, %2, %0;" : "+l"(acc) : "l"(a), "l"(b));
}
__device__ __forceinline__ void unpack2(unsigned long long v, float& lo, float& hi) {
    asm("mov.b64 {%0, %1}, %2;" : "=f"(lo), "=f"(hi) : "l"(v));
}

// ---------------------------------------------------------------------------
// K1: x (B, C_IN, N) -> g_xT (C_IN, N, B). Tiled 32x32 transpose per c-plane.
// ---------------------------------------------------------------------------
__global__ __launch_bounds__(256) void transpose_x_kernel(const float* __restrict__ x)
{
    __shared__ float tile[32][33];
    const int c  = blockIdx.z;
    const int n0 = blockIdx.x * 32;
    const int b0 = blockIdx.y * 32;
    const int tx = threadIdx.x;
    #pragma unroll
    for (int j = threadIdx.y; j < 32; j += 8)
        tile[j][tx] = x[((size_t)(b0 + j) * C_IN_ + c) * N_ + n0 + tx];
    __syncthreads();
    #pragma unroll
    for (int j = threadIdx.y; j < 32; j += 8)
        g_xT[((size_t)c * N_ + n0 + j) * B_ + b0 + tx] = tile[tx][j];
}

// ---------------------------------------------------------------------------
// K2: main compute. Lanes along b (fully coalesced gather from g_xT).
// Block = 256 threads = all of B. Each block processes NPB consecutive n.
// All per-n metadata (s, idx[k]) and weight reads are warp-uniform broadcasts.
// ---------------------------------------------------------------------------
__global__ __launch_bounds__(THREADS)
void lattice_main_kernel(const int*   __restrict__ nbr,
                         const int*   __restrict__ sub_ids,
                         const float* __restrict__ weight,
                         const float* __restrict__ bias)
{
    __shared__ __align__(16) unsigned long long sw[S_ * WPAIRS_PER_S]; // 4608 B
    __shared__ __align__(16) unsigned long long sb[S_ * WPAIRS_PER_CK];

    const int b = threadIdx.x;

    {   // weight layout (s,c,k,d) is d-innermost -> raw copy = packed f32x2
        float* swf = reinterpret_cast<float*>(sw);
        #pragma unroll
        for (int i = b; i < W_ELEMS; i += THREADS) swf[i] = weight[i];
        float* sbf = reinterpret_cast<float*>(sb);
        if (b < S_ * C_OUT_) sbf[b] = bias[b];
    }
    __syncthreads();

    const int n_base = blockIdx.x * NPB;
    const float* xb = g_xT + b;

    #pragma unroll 1
    for (int i = 0; i < NPB; ++i) {
        const int n = n_base + i;
        const int s = __ldg(&sub_ids[n]);   // uniform across block

        int rowoff[K_];
        #pragma unroll
        for (int k = 0; k < K_; ++k)
            rowoff[k] = __ldg(&nbr[n * K_ + k]) * B_;  // uniform

        unsigned long long acc0 = sb[s * WPAIRS_PER_CK + 0];
        unsigned long long acc1 = sb[s * WPAIRS_PER_CK + 1];
        unsigned long long acc2 = sb[s * WPAIRS_PER_CK + 2];
        unsigned long long acc3 = sb[s * WPAIRS_PER_CK + 3];

        const unsigned long long* wrow = sw + s * WPAIRS_PER_S;

        #pragma unroll
        for (int c = 0; c < C_IN_; ++c) {
            const float* xc = xb + (size_t)c * (N_ * B_);
            #pragma unroll
            for (int k = 0; k < K_; ++k) {
                const float xv = __ldg(xc + rowoff[k]);     // coalesced 128B line
                const unsigned long long x2 = splat2(xv);
                const unsigned long long* w4 = wrow + (c * K_ + k) * WPAIRS_PER_CK;
                const ulonglong2 wa = *reinterpret_cast<const ulonglong2*>(w4);     // broadcast
                const ulonglong2 wb = *reinterpret_cast<const ulonglong2*>(w4 + 2); // broadcast
                fma2(acc0, x2, wa.x);
                fma2(acc1, x2, wa.y);
                fma2(acc2, x2, wb.x);
                fma2(acc3, x2, wb.y);
            }
        }

        // outT (d, n, b): coalesced 128B stores per (d,n)
        float lo, hi;
        float* ob = g_outT + (size_t)n * B_ + b;
        unpack2(acc0, lo, hi);
        ob[0 * (N_ * B_)] = lo;  ob[1 * (size_t)(N_ * B_)] = hi;
        unpack2(acc1, lo, hi);
        ob[2 * (size_t)(N_ * B_)] = lo;  ob[3 * (size_t)(N_ * B_)] = hi;
        unpack2(acc2, lo, hi);
        ob[4 * (size_t)(N_ * B_)] = lo;  ob[5 * (size_t)(N_ * B_)] = hi;
        unpack2(acc3, lo, hi);
        ob[6 * (size_t)(N_ * B_)] = lo;  ob[7 * (size_t)(N_ * B_)] = hi;
    }
}

// ---------------------------------------------------------------------------
// K3: g_outT (C_OUT, N, B) -> out (B, C_OUT, N). Tiled 32x32 per d-plane.
// ---------------------------------------------------------------------------
__global__ __launch_bounds__(256) void transpose_out_kernel(float* __restrict__ out)
{
    __shared__ float tile[32][33];
    const int d  = blockIdx.z;
    const int n0 = blockIdx.x * 32;
    const int b0 = blockIdx.y * 32;
    const int tx = threadIdx.x;
    #pragma unroll
    for (int j = threadIdx.y; j < 32; j += 8)
        tile[j][tx] = g_outT[((size_t)d * N_ + n0 + j) * B_ + b0 + tx];
    __syncthreads();
    #pragma unroll
    for (int j = threadIdx.y; j < 32; j += 8)
        out[((size_t)(b0 + j) * C_OUT_ + d) * N_ + n0 + tx] = tile[tx][j];
}

extern "C" void kernel_launch(void* const* d_in, const int* in_sizes, int n_in,
                              void* d_out, int out_size)
{
    const float* x       = (const float*)d_in[0];   // (B, C_IN, N) f32
    const int*   nbr     = (const int*)  d_in[1];   // (N, K) i32
    const int*   sub_ids = (const int*)  d_in[2];   // (N,) i32
    const float* weight  = (const float*)d_in[3];   // (S, C_IN, K, C_OUT) f32
    const float* bias    = (const float*)d_in[4];   // (S, C_OUT) f32
    float*       out     = (float*)d_out;           // (B, C_OUT, N) f32

    dim3 tgrid(N_ / 32, B_ / 32, C_IN_);
    dim3 tblk(32, 8);
    transpose_x_kernel<<<tgrid, tblk>>>(x);

    lattice_main_kernel<<<N_ / NPB, THREADS>>>(nbr, sub_ids, weight, bias);

    dim3 ogrid(N_ / 32, B_ / 32, C_OUT_);
    transpose_out_kernel<<<ogrid, tblk>>>(out);
}

// round 3
// speedup vs baseline: 2.7466x; 1.2118x over previous
#include <cuda_runtime.h>

// Problem constants
#define B_     256
#define C_IN_  8
#define N_     4096
#define K_     9
#define S_     2
#define C_OUT_ 8

#define NB_    (N_ * B_)

#define WPAIRS_PER_CK 4    // C_OUT/2 f32x2 pairs per (s,c,k)
#define WPAIRS_PER_S  (C_IN_ * K_ * WPAIRS_PER_CK)   // 288
#define W_ELEMS       (S_ * C_IN_ * K_ * C_OUT_)     // 1152 floats

// Scratch (device global: allocation-free rule)
__device__ float g_xT[C_IN_ * N_ * B_];     // (c, n, b)  33.5 MB

__device__ __forceinline__ unsigned long long splat2(float v) {
    unsigned long long r;
    asm("mov.b64 %0, {%1, %1};" : "=l"(r) : "f"(v));
    return r;
}
__device__ __forceinline__ void fma2(unsigned long long& acc,
                                     unsigned long long a,
                                     unsigned long long b) {
    asm("fma.rn.f32x2 %0, %1, %2, %0;" : "+l"(acc) : "l"(a), "l"(b));
}
__device__ __forceinline__ void unpack2(unsigned long long v, float& lo, float& hi) {
    asm("mov.b64 {%0, %1}, %2;" : "=f"(lo), "=f"(hi) : "l"(v));
}

// ---------------------------------------------------------------------------
// K1: x (B, C_IN, N) -> g_xT (C_IN, N, B). float4 both directions.
// Tile: 128 n x 32 b per block. grid (N/128, B/32, C_IN), block (32, 8).
// ---------------------------------------------------------------------------
__global__ __launch_bounds__(256) void transpose_x_kernel(const float* __restrict__ x)
{
    __shared__ float tile[128][33];
    const int c  = blockIdx.z;
    const int n0 = blockIdx.x * 128;
    const int b0 = blockIdx.y * 32;
    const int tx = threadIdx.x;      // 0..31 -> n/4 index
    const int ty = threadIdx.y;      // 0..7

    // Load: each thread 4 iterations, one float4 (4 consecutive n) each.
    #pragma unroll
    for (int j = 0; j < 4; ++j) {
        const int b = ty + 8 * j;
        const float4 v = *reinterpret_cast<const float4*>(
            x + ((size_t)(b0 + b) * C_IN_ + c) * N_ + n0 + 4 * tx);
        tile[4 * tx + 0][b] = v.x;
        tile[4 * tx + 1][b] = v.y;
        tile[4 * tx + 2][b] = v.z;
        tile[4 * tx + 3][b] = v.w;
    }
    __syncthreads();

    // Store: float4 along b. g = j*256 + tid ; n = g/8 ; q = g%8 (b-quad)
    const int tid = ty * 32 + tx;
    #pragma unroll
    for (int j = 0; j < 4; ++j) {
        const int g = j * 256 + tid;
        const int n = g >> 3;
        const int q = g & 7;
        float4 v;
        v.x = tile[n][4 * q + 0];
        v.y = tile[n][4 * q + 1];
        v.z = tile[n][4 * q + 2];
        v.w = tile[n][4 * q + 3];
        *reinterpret_cast<float4*>(
            g_xT + ((size_t)c * N_ + n0 + n) * B_ + b0 + 4 * q) = v;
    }
}

// ---------------------------------------------------------------------------
// K2: fused main compute + output transpose.
// Block = 256 threads = 8 warps. lanes = 32 consecutive b (b0 + lane).
// Warp w handles n_local = 4w .. 4w+3. Gather from g_xT is one full 128B
// line per warp-LDG. Results staged in XOR-swizzled smem, then stored
// directly to out (B, C_OUT, N) as coalesced 128B rows of 32 n.
// grid (N/32, B/32).
// ---------------------------------------------------------------------------
__global__ __launch_bounds__(256)
void lattice_main_kernel(const int*   __restrict__ nbr,
                         const int*   __restrict__ sub_ids,
                         const float* __restrict__ weight,
                         const float* __restrict__ bias,
                         float*       __restrict__ out)
{
    __shared__ __align__(16) unsigned long long sw[S_ * WPAIRS_PER_S]; // 4608 B
    __shared__ __align__(16) unsigned long long sb[S_ * WPAIRS_PER_CK];
    __shared__ float sout[C_OUT_][32][32];                             // 32 KB

    const int tid  = threadIdx.x;
    const int lane = tid & 31;
    const int wid  = tid >> 5;

    {   // weight layout (s,c,k,d) is d-innermost -> raw copy = packed f32x2
        float* swf = reinterpret_cast<float*>(sw);
        #pragma unroll
        for (int i = tid; i < W_ELEMS; i += 256) swf[i] = weight[i];
        float* sbf = reinterpret_cast<float*>(sb);
        if (tid < S_ * C_OUT_) sbf[tid] = bias[tid];
    }
    __syncthreads();

    const int n0 = blockIdx.x * 32;
    const int b0 = blockIdx.y * 32;
    const float* xb = g_xT + b0 + lane;

    #pragma unroll 1
    for (int i = 0; i < 4; ++i) {
        const int nl = wid * 4 + i;
        const int n  = n0 + nl;
        const int s  = __ldg(&sub_ids[n]);   // uniform across warp

        int rowoff[K_];
        #pragma unroll
        for (int k = 0; k < K_; ++k)
            rowoff[k] = __ldg(&nbr[n * K_ + k]) * B_;  // uniform

        unsigned long long acc0 = sb[s * WPAIRS_PER_CK + 0];
        unsigned long long acc1 = sb[s * WPAIRS_PER_CK + 1];
        unsigned long long acc2 = sb[s * WPAIRS_PER_CK + 2];
        unsigned long long acc3 = sb[s * WPAIRS_PER_CK + 3];

        const unsigned long long* wrow = sw + s * WPAIRS_PER_S;

        #pragma unroll
        for (int c = 0; c < C_IN_; ++c) {
            const float* xc = xb + (size_t)c * NB_;
            #pragma unroll
            for (int k = 0; k < K_; ++k) {
                const float xv = __ldg(xc + rowoff[k]);     // 1 x 128B line
                const unsigned long long x2 = splat2(xv);
                const unsigned long long* w4 = wrow + (c * K_ + k) * WPAIRS_PER_CK;
                const ulonglong2 wa = *reinterpret_cast<const ulonglong2*>(w4);     // bcast
                const ulonglong2 wb = *reinterpret_cast<const ulonglong2*>(w4 + 2); // bcast
                fma2(acc0, x2, wa.x);
                fma2(acc1, x2, wa.y);
                fma2(acc2, x2, wb.x);
                fma2(acc3, x2, wb.y);
            }
        }

        // Stage into swizzled smem: sout[d][nl][lane ^ nl] — conflict-free.
        const int col = lane ^ nl;
        float lo, hi;
        unpack2(acc0, lo, hi);
        sout[0][nl][col] = lo;  sout[1][nl][col] = hi;
        unpack2(acc1, lo, hi);
        sout[2][nl][col] = lo;  sout[3][nl][col] = hi;
        unpack2(acc2, lo, hi);
        sout[4][nl][col] = lo;  sout[5][nl][col] = hi;
        unpack2(acc3, lo, hi);
        sout[6][nl][col] = lo;  sout[7][nl][col] = hi;
    }
    __syncthreads();

    // Epilogue: 256 (b_local, d) rows, 8 warps x 32 rows.
    // Row r: lane reads sout[d][lane][bl ^ lane] (conflict-free), stores
    // out[(b*8+d)*N + n0 + lane] — one coalesced 128B line per row.
    #pragma unroll
    for (int it = 0; it < 32; ++it) {
        const int r  = wid * 32 + it;
        const int d  = r & 7;
        const int bl = r >> 3;
        const float v = sout[d][lane][bl ^ lane];
        out[((size_t)(b0 + bl) * C_OUT_ + d) * N_ + n0 + lane] = v;
    }
}

extern "C" void kernel_launch(void* const* d_in, const int* in_sizes, int n_in,
                              void* d_out, int out_size)
{
    const float* x       = (const float*)d_in[0];   // (B, C_IN, N) f32
    const int*   nbr     = (const int*)  d_in[1];   // (N, K) i32
    const int*   sub_ids = (const int*)  d_in[2];   // (N,) i32
    const float* weight  = (const float*)d_in[3];   // (S, C_IN, K, C_OUT) f32
    const float* bias    = (const float*)d_in[4];   // (S, C_OUT) f32
    float*       out     = (float*)d_out;           // (B, C_OUT, N) f32

    dim3 tgrid(N_ / 128, B_ / 32, C_IN_);
    dim3 tblk(32, 8);
    transpose_x_kernel<<<tgrid, tblk>>>(x);

    dim3 mgrid(N_ / 32, B_ / 32);
    lattice_main_kernel<<<mgrid, 256>>>(nbr, sub_ids, weight, bias, out);
}

// round 4
// speedup vs baseline: 3.7008x; 1.3474x over previous
#include <cuda_runtime.h>

// Problem constants
#define B_     256
#define C_IN_  8
#define N_     4096
#define K_     9
#define S_     2
#define C_OUT_ 8

#define NB_    (N_ * B_)

#define WPAIRS_PER_CK 4    // C_OUT/2 f32x2 pairs per (s,c,k)
#define WPAIRS_PER_S  (C_IN_ * K_ * WPAIRS_PER_CK)   // 288
#define W_ELEMS       (S_ * C_IN_ * K_ * C_OUT_)     // 1152 floats

// Main-kernel tiling: 16 n x 64 b per block (8 warps; warp = 1 n x 64 b, 2 n serially)
#define NT  16
#define BT  64

// Scratch (device global: allocation-free rule)
__device__ float g_xT[C_IN_ * N_ * B_];     // (c, n, b)  33.5 MB

__device__ __forceinline__ unsigned long long splat2(float v) {
    unsigned long long r;
    asm("mov.b64 %0, {%1, %1};" : "=l"(r) : "f"(v));
    return r;
}
__device__ __forceinline__ void fma2(unsigned long long& acc,
                                     unsigned long long a,
                                     unsigned long long b) {
    asm("fma.rn.f32x2 %0, %1, %2, %0;" : "+l"(acc) : "l"(a), "l"(b));
}
__device__ __forceinline__ void unpack2(unsigned long long v, float& lo, float& hi) {
    asm("mov.b64 {%0, %1}, %2;" : "=f"(lo), "=f"(hi) : "l"(v));
}

// ---------------------------------------------------------------------------
// K1: x (B, C_IN, N) -> g_xT (C_IN, N, B). float4 both directions.
// Tile: 128 n x 32 b per block. grid (N/128, B/32, C_IN), block (32, 8).
// ---------------------------------------------------------------------------
__global__ __launch_bounds__(256) void transpose_x_kernel(const float* __restrict__ x)
{
    __shared__ float tile[128][33];
    const int c  = blockIdx.z;
    const int n0 = blockIdx.x * 128;
    const int b0 = blockIdx.y * 32;
    const int tx = threadIdx.x;      // 0..31
    const int ty = threadIdx.y;      // 0..7

    #pragma unroll
    for (int j = 0; j < 4; ++j) {
        const int b = ty + 8 * j;
        const float4 v = *reinterpret_cast<const float4*>(
            x + ((size_t)(b0 + b) * C_IN_ + c) * N_ + n0 + 4 * tx);
        tile[4 * tx + 0][b] = v.x;
        tile[4 * tx + 1][b] = v.y;
        tile[4 * tx + 2][b] = v.z;
        tile[4 * tx + 3][b] = v.w;
    }
    __syncthreads();

    const int tid = ty * 32 + tx;
    #pragma unroll
    for (int j = 0; j < 4; ++j) {
        const int g = j * 256 + tid;
        const int n = g >> 3;
        const int q = g & 7;
        float4 v;
        v.x = tile[n][4 * q + 0];
        v.y = tile[n][4 * q + 1];
        v.z = tile[n][4 * q + 2];
        v.w = tile[n][4 * q + 3];
        *reinterpret_cast<float4*>(
            g_xT + ((size_t)c * N_ + n0 + n) * B_ + b0 + 4 * q) = v;
    }
}

// ---------------------------------------------------------------------------
// K2: fused main compute + output transpose.
// Block = 256 threads = 8 warps, tile = 16 n x 64 b.
// Warp w: n_local in {2w, 2w+1} (serial); each lane covers b0+lane and
// b0+lane+32. Per (c,k): 2 coalesced LDG + 2 broadcast LDS.128 + 8 FFMA2 —
// weight-LDS amortized over 64 b.
// Epilogue: padded smem tile (stride 65), direct coalesced stores to out.
// grid (N/16, B/64) = 1024 blocks.
// ---------------------------------------------------------------------------
__global__ __launch_bounds__(256, 3)
void lattice_main_kernel(const int*   __restrict__ nbr,
                         const int*   __restrict__ sub_ids,
                         const float* __restrict__ weight,
                         const float* __restrict__ bias,
                         float*       __restrict__ out)
{
    __shared__ __align__(16) unsigned long long sw[S_ * WPAIRS_PER_S]; // 4608 B
    __shared__ __align__(16) unsigned long long sb[S_ * WPAIRS_PER_CK];
    __shared__ float sout[C_OUT_][NT][BT + 1];                          // ~33 KB

    const int tid  = threadIdx.x;
    const int lane = tid & 31;
    const int wid  = tid >> 5;

    {   // weight layout (s,c,k,d) is d-innermost -> raw copy = packed f32x2
        float* swf = reinterpret_cast<float*>(sw);
        #pragma unroll
        for (int i = tid; i < W_ELEMS; i += 256) swf[i] = weight[i];
        float* sbf = reinterpret_cast<float*>(sb);
        if (tid < S_ * C_OUT_) sbf[tid] = bias[tid];
    }
    __syncthreads();

    const int n0 = blockIdx.x * NT;
    const int b0 = blockIdx.y * BT;
    const float* xb = g_xT + b0 + lane;

    #pragma unroll 1
    for (int i = 0; i < 2; ++i) {
        const int nl = wid * 2 + i;
        const int n  = n0 + nl;
        const int s  = __ldg(&sub_ids[n]);   // uniform across warp

        int rowoff[K_];
        #pragma unroll
        for (int k = 0; k < K_; ++k)
            rowoff[k] = __ldg(&nbr[n * K_ + k]) * B_;  // uniform

        // accA: b = b0+lane ; accB: b = b0+lane+32
        unsigned long long accA0 = sb[s * WPAIRS_PER_CK + 0];
        unsigned long long accA1 = sb[s * WPAIRS_PER_CK + 1];
        unsigned long long accA2 = sb[s * WPAIRS_PER_CK + 2];
        unsigned long long accA3 = sb[s * WPAIRS_PER_CK + 3];
        unsigned long long accB0 = accA0, accB1 = accA1;
        unsigned long long accB2 = accA2, accB3 = accA3;

        const unsigned long long* wrow = sw + s * WPAIRS_PER_S;

        #pragma unroll
        for (int c = 0; c < C_IN_; ++c) {
            const float* xc = xb + (size_t)c * NB_;
            #pragma unroll
            for (int k = 0; k < K_; ++k) {
                const float xv0 = __ldg(xc + rowoff[k]);        // 128B line
                const float xv1 = __ldg(xc + rowoff[k] + 32);   // adjacent line
                const unsigned long long x0 = splat2(xv0);
                const unsigned long long x1 = splat2(xv1);
                const unsigned long long* w4 = wrow + (c * K_ + k) * WPAIRS_PER_CK;
                const ulonglong2 wa = *reinterpret_cast<const ulonglong2*>(w4);     // bcast
                const ulonglong2 wb = *reinterpret_cast<const ulonglong2*>(w4 + 2); // bcast
                fma2(accA0, x0, wa.x);
                fma2(accA1, x0, wa.y);
                fma2(accA2, x0, wb.x);
                fma2(accA3, x0, wb.y);
                fma2(accB0, x1, wa.x);
                fma2(accB1, x1, wa.y);
                fma2(accB2, x1, wb.x);
                fma2(accB3, x1, wb.y);
            }
        }

        // Stage: write columns lane and lane+32 of row (d, nl) — stride-1,
        // conflict-free (row stride 65 ≡ 1 mod 32).
        float lo, hi;
        unpack2(accA0, lo, hi); sout[0][nl][lane] = lo; sout[1][nl][lane] = hi;
        unpack2(accA1, lo, hi); sout[2][nl][lane] = lo; sout[3][nl][lane] = hi;
        unpack2(accA2, lo, hi); sout[4][nl][lane] = lo; sout[5][nl][lane] = hi;
        unpack2(accA3, lo, hi); sout[6][nl][lane] = lo; sout[7][nl][lane] = hi;
        unpack2(accB0, lo, hi); sout[0][nl][lane+32] = lo; sout[1][nl][lane+32] = hi;
        unpack2(accB1, lo, hi); sout[2][nl][lane+32] = lo; sout[3][nl][lane+32] = hi;
        unpack2(accB2, lo, hi); sout[4][nl][lane+32] = lo; sout[5][nl][lane+32] = hi;
        unpack2(accB3, lo, hi); sout[6][nl][lane+32] = lo; sout[7][nl][lane+32] = hi;
    }
    __syncthreads();

    // Epilogue: warp w owns d = w. 64 bl values as 32 half-warp pairs
    // (bl, bl+16) -> disjoint bank sets under the stride-65 padding.
    {
        const int d = wid;
        #pragma unroll
        for (int p = 0; p < 32; ++p) {
            const int blA = p + (p & 16);             // 0..15, 32..47
            const int bl  = (lane < 16) ? blA : blA + 16;
            const int nn  = lane & 15;
            const float v = sout[d][nn][bl];
            out[((size_t)(b0 + bl) * C_OUT_ + d) * N_ + n0 + nn] = v;
        }
    }
}

extern "C" void kernel_launch(void* const* d_in, const int* in_sizes, int n_in,
                              void* d_out, int out_size)
{
    const float* x       = (const float*)d_in[0];   // (B, C_IN, N) f32
    const int*   nbr     = (const int*)  d_in[1];   // (N, K) i32
    const int*   sub_ids = (const int*)  d_in[2];   // (N,) i32
    const float* weight  = (const float*)d_in[3];   // (S, C_IN, K, C_OUT) f32
    const float* bias    = (const float*)d_in[4];   // (S, C_OUT) f32
    float*       out     = (float*)d_out;           // (B, C_OUT, N) f32

    dim3 tgrid(N_ / 128, B_ / 32, C_IN_);
    dim3 tblk(32, 8);
    transpose_x_kernel<<<tgrid, tblk>>>(x);

    dim3 mgrid(N_ / NT, B_ / BT);
    lattice_main_kernel<<<mgrid, 256>>>(nbr, sub_ids, weight, bias, out);
}